// round 16
// baseline (speedup 1.0000x reference)
#include <cuda_runtime.h>
#include <cstdint>

// Instant-NGP hash-grid encoding, 16 levels, 2 features/level.
// R16: hashed-level aligned-quad gathers. idx(x+1) = idx(x) ^ (x^(x+1)), and
// the xor-mask is <4 for 75% of x, so both x-corners sit in the same aligned
// 32B 4-entry block of the ORIGINAL table. LDG.256 fetches the block (1
// line/lane, same as before); only x%4==3 lanes (25%) need the extra
// predicated fetch. Kept: dense quad table + LDG.256, smem-staged stores.

#define THREADS 256

// ---- dense quad-table scratch (repacked every launch; deterministic) ----
// entry u (32B): [T(u%s), T((u+1)%s), T((u+res)%s), T((u+res+1)%s)]
#define TOTAL_D4 489388
__device__ __align__(32) unsigned long long g_dense2[TOTAL_D4 * 4];   // 15.7 MB

__constant__ uint32_t c_DOFF4[6] = {0u, 4370u, 15526u, 38292u, 90356u, 210464u};

__global__ __launch_bounds__(256)
void repack_dense_kernel(const float* __restrict__ table)
{
    const uint32_t SIZE[6] = {4096u, 10648u, 21952u, 50656u, 117656u, 274632u};
    const uint32_t OFF[6]  = {0u, 4096u, 14744u, 36696u, 87352u, 205008u};
    const uint32_t RESL[6] = {16u, 22u, 28u, 37u, 49u, 65u};
    int t = blockIdx.x * 256 + threadIdx.x;
    if (t >= TOTAL_D4) return;
    int l = 0;
    if (t >= (int)c_DOFF4[1]) l = 1;
    if (t >= (int)c_DOFF4[2]) l = 2;
    if (t >= (int)c_DOFF4[3]) l = 3;
    if (t >= (int)c_DOFF4[4]) l = 4;
    if (t >= (int)c_DOFF4[5]) l = 5;
    const uint32_t u   = (uint32_t)t - c_DOFF4[l];
    const uint32_t s   = SIZE[l];
    const uint32_t res = RESL[l];
    const float2* tb = ((const float2*)table) + OFF[l];
    const float2 f00 = tb[u % s];
    const float2 f10 = tb[(u + 1u) % s];
    const float2 f01 = tb[(u + res) % s];
    const float2 f11 = tb[(u + res + 1u) % s];
    float4* dst = (float4*)(g_dense2 + (size_t)t * 4);
    dst[0] = make_float4(f00.x, f00.y, f10.x, f10.y);
    dst[1] = make_float4(f01.x, f01.y, f11.x, f11.y);
}

// ---- 256-bit load (sm_100a) ----
struct Q8 { uint64_t a, b, c, d; };
__device__ __forceinline__ Q8 ld256(const unsigned long long* p) {
    Q8 q;
    asm("ld.global.nc.v4.u64 {%0,%1,%2,%3}, [%4];"
        : "=l"(q.a), "=l"(q.b), "=l"(q.c), "=l"(q.d) : "l"(p));
    return q;
}

// predicated 8B gather: lanes with pred==0 issue nothing
__device__ __forceinline__ uint64_t ldg_pred(const unsigned long long* p, uint32_t pred) {
    uint64_t r = 0;
    asm("{\n\t"
        ".reg .pred q;\n\t"
        "setp.ne.u32 q, %1, 0;\n\t"
        "@q ld.global.nc.b64 %0, [%2];\n\t"
        "}" : "+l"(r) : "r"(pred), "l"(p));
    return r;
}

// select entry k (0..3) from an aligned quad
__device__ __forceinline__ uint64_t sel4(const Q8& q, uint32_t k) {
    const uint64_t lo = (k & 1u) ? q.b : q.a;
    const uint64_t hi = (k & 1u) ? q.d : q.c;
    return (k & 2u) ? hi : lo;
}

// ---- packed f32x2 helpers (sm_100+) ----
__device__ __forceinline__ uint64_t mul2(uint64_t a, uint64_t b) {
    uint64_t r; asm("mul.rn.f32x2 %0, %1, %2;" : "=l"(r) : "l"(a), "l"(b)); return r;
}
__device__ __forceinline__ uint64_t fma2(uint64_t a, uint64_t b, uint64_t c) {
    uint64_t r; asm("fma.rn.f32x2 %0, %1, %2, %3;" : "=l"(r) : "l"(a), "l"(b), "l"(c)); return r;
}
__device__ __forceinline__ uint64_t pack2(float x) {
    uint64_t r; asm("mov.b64 %0, {%1, %1};" : "=l"(r) : "f"(x)); return r;
}
__device__ __forceinline__ uint64_t lerp2p(uint64_t a, uint64_t b, uint64_t t2, uint64_t omt2) {
    return fma2(t2, b, mul2(omt2, a));
}

struct Coords { float tx, ty, tz; uint32_t gx, gy, gz; };

__device__ __forceinline__ Coords mk_coords(float px, float py, float pz, float s) {
    Coords c;
    const float sx = __fadd_rn(__fmul_rn(px, s), 0.5f);
    const float sy = __fadd_rn(__fmul_rn(py, s), 0.5f);
    const float sz = __fadd_rn(__fmul_rn(pz, s), 0.5f);
    const float fx = floorf(sx), fy = floorf(sy), fz = floorf(sz);
    c.tx = sx - fx; c.ty = sy - fy; c.tz = sz - fz;
    c.gx = (uint32_t)fx; c.gy = (uint32_t)fy; c.gz = (uint32_t)fz;
    return c;
}

__device__ __forceinline__ uint64_t trilerp(uint64_t f0, uint64_t f1, uint64_t f2, uint64_t f3,
                                            uint64_t f4, uint64_t f5, uint64_t f6, uint64_t f7,
                                            float tx, float ty, float tz)
{
    const uint64_t tx2 = pack2(tx), omx = pack2(1.0f - tx);
    const uint64_t ty2 = pack2(ty), omy = pack2(1.0f - ty);
    const uint64_t tz2 = pack2(tz), omz = pack2(1.0f - tz);
    uint64_t cx0 = lerp2p(f0, f1, tx2, omx);
    uint64_t cx1 = lerp2p(f2, f3, tx2, omx);
    uint64_t cx2 = lerp2p(f4, f5, tx2, omx);
    uint64_t cx3 = lerp2p(f6, f7, tx2, omx);
    uint64_t cy0 = lerp2p(cx0, cx1, ty2, omy);
    uint64_t cy1 = lerp2p(cx2, cx3, ty2, omy);
    return lerp2p(cy0, cy1, tz2, omz);
}

// Per-warp staging: 32 rows x 36 floats (144B stride)
#define ROW_F 36

__global__ __launch_bounds__(THREADS, 2)
void hash_encode_kernel(const float* __restrict__ pos,
                        const float* __restrict__ table,
                        float* __restrict__ out,
                        int n)
{
    __shared__ __align__(16) float stage[8][32 * ROW_F];   // 36.9 KB

    const int i = blockIdx.x * THREADS + threadIdx.x;
    if (i >= n) return;                       // n % 8192 == 0: warp-uniform
    const int wid  = threadIdx.x >> 5;
    const int lane = threadIdx.x & 31;

    const float SCALE[16] = {
        15.0f,           20.1121272169f,  26.8576197265f,  35.7583507266f,
        47.5029360517f,  63.0000097696f,  83.4485217584f,  110.4304959160f,
        146.0334253520f, 193.0117738230f, 255.0000781570f, 336.7941385900f,
        444.7220517000f, 587.1337911820f, 775.0472137460f, 1023.0004689400f
    };
    const uint32_t RES[6]   = {16u, 22u, 28u, 37u, 49u, 65u};
    const uint32_t DOFF4[6] = {0u, 4370u, 15526u, 38292u, 90356u, 210464u};
    const uint32_t OFF_H[16] = {
        0u,0u,0u,0u,0u,0u,
        479640u, 1003928u, 1528216u, 2052504u, 2576792u,
        3101080u, 3625368u, 4149656u, 4673944u, 5198232u
    };

    const float px = pos[3 * i + 0];
    const float py = pos[3 * i + 1];
    const float pz = pos[3 * i + 2];

    const unsigned long long* __restrict__ tb64 = (const unsigned long long*)table;
    ulonglong2* __restrict__ myrow = (ulonglong2*)&stage[wid][lane * ROW_F];

    // ---- dense levels 0..5: quad table, 2 x LDG.256 per level ----
    #pragma unroll
    for (int lp = 0; lp < 3; ++lp) {
        const int lA = 2 * lp, lB = lA + 1;
        const Coords cA = mk_coords(px, py, pz, SCALE[lA]);
        const Coords cB = mk_coords(px, py, pz, SCALE[lB]);

        const uint32_t rA = RES[lA], rA2 = rA * rA;
        const uint32_t bA = cA.gx + cA.gy * rA + cA.gz * rA2;
        const unsigned long long* qA = g_dense2 + (size_t)(DOFF4[lA] + bA) * 4;
        Q8 A0 = ld256(qA);
        Q8 A1 = ld256(qA + (size_t)rA2 * 4);

        const uint32_t rB = RES[lB], rB2 = rB * rB;
        const uint32_t bB = cB.gx + cB.gy * rB + cB.gz * rB2;
        const unsigned long long* qB = g_dense2 + (size_t)(DOFF4[lB] + bB) * 4;
        Q8 B0 = ld256(qB);
        Q8 B1 = ld256(qB + (size_t)rB2 * 4);

        uint64_t resA = trilerp(A0.a, A0.b, A0.c, A0.d, A1.a, A1.b, A1.c, A1.d,
                                cA.tx, cA.ty, cA.tz);
        uint64_t resB = trilerp(B0.a, B0.b, B0.c, B0.d, B1.a, B1.b, B1.c, B1.d,
                                cB.tx, cB.ty, cB.tz);
        ulonglong2 st; st.x = resA; st.y = resB;
        myrow[lp] = st;
    }

    // ---- hashed levels 6..15: aligned-quad x-pair ----
    const uint32_t P2 = 2654435761u;
    const uint32_t P3 = 805459861u;
    const uint32_t MASK = 524287u;

    uint64_t r_even = 0;

    #pragma unroll
    for (int l = 6; l < 16; ++l) {
        const Coords c = mk_coords(px, py, pz, SCALE[l]);
        const unsigned long long* tb = tb64 + OFF_H[l];   // 32B-aligned (off%4==0)

        const uint32_t x0 = c.gx;
        const uint32_t xorm = x0 ^ (x0 + 1u);             // 1,3,7,15,... (bits < 2^19)
        const uint32_t outb = (x0 & 3u) == 3u ? 1u : 0u;  // x1 leaves the 4-block

        const uint32_t y0 = c.gy * P2, y1 = y0 + P2;
        const uint32_t z0 = c.gz * P3, z1 = z0 + P3;
        const uint32_t yz0 = y0 ^ z0, yz1 = y1 ^ z0;
        const uint32_t yz2 = y0 ^ z1, yz3 = y1 ^ z1;

        const uint32_t i0 = (x0 ^ yz0) & MASK;
        const uint32_t i1 = (x0 ^ yz1) & MASK;
        const uint32_t i2 = (x0 ^ yz2) & MASK;
        const uint32_t i3 = (x0 ^ yz3) & MASK;

        // aligned 4-entry blocks: contain f(x0) always; f(x1) too unless outb
        Q8 q0 = ld256(tb + (i0 & ~3u));
        Q8 q1 = ld256(tb + (i1 & ~3u));
        Q8 q2 = ld256(tb + (i2 & ~3u));
        Q8 q3 = ld256(tb + (i3 & ~3u));

        // 25% of lanes fetch the out-of-block x1 entry (idx = i ^ xorm exactly)
        uint64_t t0 = ldg_pred(tb + (i0 ^ xorm), outb);
        uint64_t t1 = ldg_pred(tb + (i1 ^ xorm), outb);
        uint64_t t2 = ldg_pred(tb + (i2 ^ xorm), outb);
        uint64_t t3 = ldg_pred(tb + (i3 ^ xorm), outb);

        const uint32_t kx = xorm & 3u;   // in-block x1 selector delta
        const uint64_t f0 = sel4(q0, i0 & 3u);
        const uint64_t f2 = sel4(q1, i1 & 3u);
        const uint64_t f4 = sel4(q2, i2 & 3u);
        const uint64_t f6 = sel4(q3, i3 & 3u);
        const uint64_t f1 = outb ? t0 : sel4(q0, (i0 & 3u) ^ kx);
        const uint64_t f3 = outb ? t1 : sel4(q1, (i1 & 3u) ^ kx);
        const uint64_t f5 = outb ? t2 : sel4(q2, (i2 & 3u) ^ kx);
        const uint64_t f7 = outb ? t3 : sel4(q3, (i3 & 3u) ^ kx);

        uint64_t r = trilerp(f0, f1, f2, f3, f4, f5, f6, f7, c.tx, c.ty, c.tz);

        if (l & 1) {
            ulonglong2 st; st.x = r_even; st.y = r;
            myrow[(l >> 1)] = st;
        } else {
            r_even = r;
        }
    }

    // ---- cooperative coalesced writeback: 4KB per warp, 4 lines/STG ----
    __syncwarp();
    const float4* s4 = (const float4*)&stage[wid][0];
    const int warp_first = blockIdx.x * THREADS + wid * 32;
    float4* o4 = ((float4*)out) + (size_t)warp_first * 8;
    #pragma unroll
    for (int k = 0; k < 8; ++k) {
        const int p = k * 4 + (lane >> 3);      // staged row
        const int w = lane & 7;                 // float4 within row
        o4[k * 32 + lane] = s4[p * (ROW_F / 4) + w];
    }
}

extern "C" void kernel_launch(void* const* d_in, const int* in_sizes, int n_in,
                              void* d_out, int out_size)
{
    const float* pos   = (const float*)d_in[0];
    const float* table = (const float*)d_in[1];
    if (n_in >= 2 && in_sizes[0] != 3145728 && in_sizes[1] == 3145728) {
        pos   = (const float*)d_in[1];
        table = (const float*)d_in[0];
    }
    const int n = out_size / 32;

    repack_dense_kernel<<<(TOTAL_D4 + 255) / 256, 256>>>(table);
    hash_encode_kernel<<<(n + THREADS - 1) / THREADS, THREADS>>>(pos, table, (float*)d_out, n);
}

// round 17
// speedup vs baseline: 1.0582x; 1.0582x over previous
#include <cuda_runtime.h>
#include <cstdint>

// Instant-NGP hash-grid encoding, 16 levels, 2 features/level.
// R17 = revert to R15 (best measured: 298.8us). R16's hashed-quad variant cost
// +48 regs -> occupancy collapse (L1 89%->77%, latency-starved). R15 keeps only
// register-cheap line reductions:
//   - dense levels: xy-quad repacked table, 2 x LDG.256 per level (2 quads live)
//   - hashed levels: 16B-pair loads (prime1==1 adjacency) + predicated x1 fetch
//   - smem-staged coalesced output writeback (4 lines/STG vs 32)

#define THREADS 256

// ---- dense quad-table scratch (repacked every launch; deterministic) ----
// entry u (32B): [T(u%s), T((u+1)%s), T((u+res)%s), T((u+res+1)%s)] (float2 each)
#define TOTAL_D4 489388
__device__ __align__(32) unsigned long long g_dense2[TOTAL_D4 * 4];   // 15.7 MB

__constant__ uint32_t c_DOFF4[6] = {0u, 4370u, 15526u, 38292u, 90356u, 210464u};

__global__ __launch_bounds__(256)
void repack_dense_kernel(const float* __restrict__ table)
{
    const uint32_t SIZE[6] = {4096u, 10648u, 21952u, 50656u, 117656u, 274632u};
    const uint32_t OFF[6]  = {0u, 4096u, 14744u, 36696u, 87352u, 205008u};
    const uint32_t RESL[6] = {16u, 22u, 28u, 37u, 49u, 65u};
    int t = blockIdx.x * 256 + threadIdx.x;
    if (t >= TOTAL_D4) return;
    int l = 0;
    if (t >= (int)c_DOFF4[1]) l = 1;
    if (t >= (int)c_DOFF4[2]) l = 2;
    if (t >= (int)c_DOFF4[3]) l = 3;
    if (t >= (int)c_DOFF4[4]) l = 4;
    if (t >= (int)c_DOFF4[5]) l = 5;
    const uint32_t u   = (uint32_t)t - c_DOFF4[l];
    const uint32_t s   = SIZE[l];
    const uint32_t res = RESL[l];
    const float2* tb = ((const float2*)table) + OFF[l];
    const float2 f00 = tb[u % s];
    const float2 f10 = tb[(u + 1u) % s];
    const float2 f01 = tb[(u + res) % s];
    const float2 f11 = tb[(u + res + 1u) % s];
    float4* dst = (float4*)(g_dense2 + (size_t)t * 4);
    dst[0] = make_float4(f00.x, f00.y, f10.x, f10.y);
    dst[1] = make_float4(f01.x, f01.y, f11.x, f11.y);
}

// ---- 256-bit load (sm_100a) ----
struct Q8 { uint64_t a, b, c, d; };
__device__ __forceinline__ Q8 ld256(const unsigned long long* p) {
    Q8 q;
    asm("ld.global.nc.v4.u64 {%0,%1,%2,%3}, [%4];"
        : "=l"(q.a), "=l"(q.b), "=l"(q.c), "=l"(q.d) : "l"(p));
    return q;
}

// predicated 8B gather: lanes with pred==0 issue nothing (no dummy line)
__device__ __forceinline__ uint64_t ldg_pred(const unsigned long long* p, uint32_t pred) {
    uint64_t r = 0;
    asm("{\n\t"
        ".reg .pred q;\n\t"
        "setp.ne.u32 q, %1, 0;\n\t"
        "@q ld.global.nc.b64 %0, [%2];\n\t"
        "}" : "+l"(r) : "r"(pred), "l"(p));
    return r;
}

// ---- packed f32x2 helpers (sm_100+) ----
__device__ __forceinline__ uint64_t mul2(uint64_t a, uint64_t b) {
    uint64_t r; asm("mul.rn.f32x2 %0, %1, %2;" : "=l"(r) : "l"(a), "l"(b)); return r;
}
__device__ __forceinline__ uint64_t fma2(uint64_t a, uint64_t b, uint64_t c) {
    uint64_t r; asm("fma.rn.f32x2 %0, %1, %2, %3;" : "=l"(r) : "l"(a), "l"(b), "l"(c)); return r;
}
__device__ __forceinline__ uint64_t pack2(float x) {
    uint64_t r; asm("mov.b64 %0, {%1, %1};" : "=l"(r) : "f"(x)); return r;
}
__device__ __forceinline__ uint64_t lerp2p(uint64_t a, uint64_t b, uint64_t t2, uint64_t omt2) {
    return fma2(t2, b, mul2(omt2, a));
}

struct Coords { float tx, ty, tz; uint32_t gx, gy, gz; };

__device__ __forceinline__ Coords mk_coords(float px, float py, float pz, float s) {
    Coords c;
    const float sx = __fadd_rn(__fmul_rn(px, s), 0.5f);
    const float sy = __fadd_rn(__fmul_rn(py, s), 0.5f);
    const float sz = __fadd_rn(__fmul_rn(pz, s), 0.5f);
    const float fx = floorf(sx), fy = floorf(sy), fz = floorf(sz);
    c.tx = sx - fx; c.ty = sy - fy; c.tz = sz - fz;
    c.gx = (uint32_t)fx; c.gy = (uint32_t)fy; c.gz = (uint32_t)fz;
    return c;
}

// trilinear from 8 packed-f32x2 corners (x fastest, then y, then z)
__device__ __forceinline__ uint64_t trilerp(uint64_t f0, uint64_t f1, uint64_t f2, uint64_t f3,
                                            uint64_t f4, uint64_t f5, uint64_t f6, uint64_t f7,
                                            float tx, float ty, float tz)
{
    const uint64_t tx2 = pack2(tx), omx = pack2(1.0f - tx);
    const uint64_t ty2 = pack2(ty), omy = pack2(1.0f - ty);
    const uint64_t tz2 = pack2(tz), omz = pack2(1.0f - tz);
    uint64_t cx0 = lerp2p(f0, f1, tx2, omx);
    uint64_t cx1 = lerp2p(f2, f3, tx2, omx);
    uint64_t cx2 = lerp2p(f4, f5, tx2, omx);
    uint64_t cx3 = lerp2p(f6, f7, tx2, omx);
    uint64_t cy0 = lerp2p(cx0, cx1, ty2, omy);
    uint64_t cy1 = lerp2p(cx2, cx3, ty2, omy);
    return lerp2p(cy0, cy1, tz2, omz);
}

// Per-warp staging: 32 rows x 36 floats (144B stride -> conflict-free STS/LDS.128)
#define ROW_F 36

__global__ __launch_bounds__(THREADS, 3)
void hash_encode_kernel(const float* __restrict__ pos,
                        const float* __restrict__ table,
                        float* __restrict__ out,
                        int n)
{
    __shared__ __align__(16) float stage[8][32 * ROW_F];   // 36.9 KB

    const int i = blockIdx.x * THREADS + threadIdx.x;
    if (i >= n) return;                       // n % 8192 == 0: warp-uniform
    const int wid  = threadIdx.x >> 5;
    const int lane = threadIdx.x & 31;

    const float SCALE[16] = {
        15.0f,           20.1121272169f,  26.8576197265f,  35.7583507266f,
        47.5029360517f,  63.0000097696f,  83.4485217584f,  110.4304959160f,
        146.0334253520f, 193.0117738230f, 255.0000781570f, 336.7941385900f,
        444.7220517000f, 587.1337911820f, 775.0472137460f, 1023.0004689400f
    };
    const uint32_t RES[6]   = {16u, 22u, 28u, 37u, 49u, 65u};
    const uint32_t DOFF4[6] = {0u, 4370u, 15526u, 38292u, 90356u, 210464u};
    const uint32_t OFF_H[16] = {
        0u,0u,0u,0u,0u,0u,
        479640u, 1003928u, 1528216u, 2052504u, 2576792u,
        3101080u, 3625368u, 4149656u, 4673944u, 5198232u
    };

    const float px = pos[3 * i + 0];
    const float py = pos[3 * i + 1];
    const float pz = pos[3 * i + 2];

    const unsigned long long* __restrict__ tb64 = (const unsigned long long*)table;
    ulonglong2* __restrict__ myrow = (ulonglong2*)&stage[wid][lane * ROW_F];

    // ---- dense levels 0..5: quad table, 2 x LDG.256 per level ----
    #pragma unroll
    for (int lp = 0; lp < 3; ++lp) {
        const int lA = 2 * lp, lB = lA + 1;
        const Coords cA = mk_coords(px, py, pz, SCALE[lA]);
        const Coords cB = mk_coords(px, py, pz, SCALE[lB]);

        const uint32_t rA = RES[lA], rA2 = rA * rA;
        const uint32_t bA = cA.gx + cA.gy * rA + cA.gz * rA2;
        const unsigned long long* qA = g_dense2 + (size_t)(DOFF4[lA] + bA) * 4;
        Q8 A0 = ld256(qA);
        Q8 A1 = ld256(qA + (size_t)rA2 * 4);

        const uint32_t rB = RES[lB], rB2 = rB * rB;
        const uint32_t bB = cB.gx + cB.gy * rB + cB.gz * rB2;
        const unsigned long long* qB = g_dense2 + (size_t)(DOFF4[lB] + bB) * 4;
        Q8 B0 = ld256(qB);
        Q8 B1 = ld256(qB + (size_t)rB2 * 4);

        uint64_t resA = trilerp(A0.a, A0.b, A0.c, A0.d, A1.a, A1.b, A1.c, A1.d,
                                cA.tx, cA.ty, cA.tz);
        uint64_t resB = trilerp(B0.a, B0.b, B0.c, B0.d, B1.a, B1.b, B1.c, B1.d,
                                cB.tx, cB.ty, cB.tz);
        ulonglong2 st; st.x = resA; st.y = resB;
        myrow[lp] = st;
    }

    // ---- hashed levels 6..15: x-pair via prime1==1 adjacency ----
    const uint32_t P2 = 2654435761u;
    const uint32_t P3 = 805459861u;
    const uint32_t MASK = 524287u;

    uint64_t r_even = 0;

    #pragma unroll
    for (int l = 6; l < 16; ++l) {
        const Coords c = mk_coords(px, py, pz, SCALE[l]);
        const unsigned long long* tb = tb64 + OFF_H[l];
        const ulonglong2* tp = (const ulonglong2*)tb;   // aligned 16B pairs

        const uint32_t x0 = c.gx, x1 = x0 + 1u;
        const uint32_t y0 = c.gy * P2, y1 = y0 + P2;
        const uint32_t z0 = c.gz * P3, z1 = z0 + P3;
        const uint32_t yz0 = y0 ^ z0, yz1 = y1 ^ z0;
        const uint32_t yz2 = y0 ^ z1, yz3 = y1 ^ z1;

        const uint32_t i0 = (x0 ^ yz0) & MASK;
        const uint32_t i1 = (x0 ^ yz1) & MASK;
        const uint32_t i2 = (x0 ^ yz2) & MASK;
        const uint32_t i3 = (x0 ^ yz3) & MASK;

        // pair blocks: contain f(x0) always; f(x1) too when x0 is even
        ulonglong2 b0 = __ldg(tp + (i0 >> 1));
        ulonglong2 b1 = __ldg(tp + (i1 >> 1));
        ulonglong2 b2 = __ldg(tp + (i2 >> 1));
        ulonglong2 b3 = __ldg(tp + (i3 >> 1));

        // odd-gx lanes fetch f(x1); even lanes issue nothing (predicated off)
        const uint32_t oddm = x0 & 1u;
        uint64_t t0 = ldg_pred(tb + ((x1 ^ yz0) & MASK), oddm);
        uint64_t t1 = ldg_pred(tb + ((x1 ^ yz1) & MASK), oddm);
        uint64_t t2 = ldg_pred(tb + ((x1 ^ yz2) & MASK), oddm);
        uint64_t t3 = ldg_pred(tb + ((x1 ^ yz3) & MASK), oddm);

        const bool odd = oddm != 0u;
        const uint64_t f0 = (i0 & 1) ? b0.y : b0.x;
        const uint64_t f2 = (i1 & 1) ? b1.y : b1.x;
        const uint64_t f4 = (i2 & 1) ? b2.y : b2.x;
        const uint64_t f6 = (i3 & 1) ? b3.y : b3.x;
        const uint64_t f1 = odd ? t0 : ((i0 & 1) ? b0.x : b0.y);
        const uint64_t f3 = odd ? t1 : ((i1 & 1) ? b1.x : b1.y);
        const uint64_t f5 = odd ? t2 : ((i2 & 1) ? b2.x : b2.y);
        const uint64_t f7 = odd ? t3 : ((i3 & 1) ? b3.x : b3.y);

        uint64_t r = trilerp(f0, f1, f2, f3, f4, f5, f6, f7, c.tx, c.ty, c.tz);

        if (l & 1) {
            ulonglong2 st; st.x = r_even; st.y = r;
            myrow[(l >> 1)] = st;
        } else {
            r_even = r;
        }
    }

    // ---- cooperative coalesced writeback: 4KB per warp, 4 lines/STG ----
    __syncwarp();
    const float4* s4 = (const float4*)&stage[wid][0];
    const int warp_first = blockIdx.x * THREADS + wid * 32;
    float4* o4 = ((float4*)out) + (size_t)warp_first * 8;
    #pragma unroll
    for (int k = 0; k < 8; ++k) {
        const int p = k * 4 + (lane >> 3);      // staged row
        const int w = lane & 7;                 // float4 within row
        o4[k * 32 + lane] = s4[p * (ROW_F / 4) + w];
    }
}

extern "C" void kernel_launch(void* const* d_in, const int* in_sizes, int n_in,
                              void* d_out, int out_size)
{
    const float* pos   = (const float*)d_in[0];
    const float* table = (const float*)d_in[1];
    if (n_in >= 2 && in_sizes[0] != 3145728 && in_sizes[1] == 3145728) {
        pos   = (const float*)d_in[1];
        table = (const float*)d_in[0];
    }
    const int n = out_size / 32;

    repack_dense_kernel<<<(TOTAL_D4 + 255) / 256, 256>>>(table);
    hash_encode_kernel<<<(n + THREADS - 1) / THREADS, THREADS>>>(pos, table, (float*)d_out, n);
}